// round 16
// baseline (speedup 1.0000x reference)
#include <cuda_runtime.h>
#include <math.h>
#include <stdint.h>

#define TTOK 8192
#define DDIM 2048
#define HDIM 8192
#define NEXP 8
#define NLIST 16
#define BM 128
#define BN 256
#define BK 32
#define NTHR 512
#define BKP 36     // A smem row stride (floats): frag banks (4*gr+tc) unique
#define BNP 264    // B smem row stride (floats): frag banks (8*tc+gr) unique
#define STAGE_F (BM * BKP + BK * BNP)       // 13056 floats = 52224 B
#define NSTAGE 3
#define SMEM_BYTES (NSTAGE * STAGE_F * 4)   // 156672 B -> 1 CTA(512t)/SM
#define MAXTILE 160

// ---------------- scratch (__device__ globals; no allocs) ------------------
__device__ int   g_cnt[NLIST];
__device__ int   g_off[NLIST];
__device__ int   g_ntile;     // total tiles (all 16 lists)
__device__ int   g_ntile0;    // tiles of slot-0 lists (prefix of table)
__device__ int   g_tileL[MAXTILE];
__device__ int   g_tileM[MAXTILE];
__device__ int   g_tok[NLIST * TTOK];
__device__ float g_gate[NLIST * TTOK];
__device__ float g_xr[(size_t)TTOK * DDIM];               // tf32-rounded x
__device__ float g_hbuf[(size_t)(2 * TTOK + BM) * HDIM];  // packed rows, tf32

// ---------------- helpers --------------------------------------------------
__device__ __forceinline__ uint32_t smem_u32(const void* p) {
    uint32_t a;
    asm("{ .reg .u64 t; cvta.to.shared.u64 t, %1; cvt.u32.u64 %0, t; }"
        : "=r"(a) : "l"(p));
    return a;
}
__device__ __forceinline__ uint32_t f2tf32(float x) {
    uint32_t r;
    asm("cvt.rna.tf32.f32 %0, %1;" : "=r"(r) : "f"(x));
    return r;
}
__device__ __forceinline__ uint32_t u2tf32(uint32_t x) {
    uint32_t r;
    asm("cvt.rna.tf32.f32 %0, %1;" : "=r"(r) : "r"(x));
    return r;
}
__device__ __forceinline__ void cpa16(uint32_t s, const void* g) {
    asm volatile("cp.async.cg.shared.global [%0], [%1], 16;"
                 :: "r"(s), "l"(g) : "memory");
}
__device__ __forceinline__ void mma8(float* c, const uint32_t* a,
                                     const uint32_t* b) {
    asm volatile(
        "mma.sync.aligned.m16n8k8.row.col.f32.tf32.tf32.f32 "
        "{%0,%1,%2,%3}, {%4,%5,%6,%7}, {%8,%9}, {%0,%1,%2,%3};"
        : "+f"(c[0]), "+f"(c[1]), "+f"(c[2]), "+f"(c[3])
        : "r"(a[0]), "r"(a[1]), "r"(a[2]), "r"(a[3]), "r"(b[0]), "r"(b[1]));
}
__device__ __forceinline__ float gelu_tanh(float v) {
    const float c = 0.7978845608028654f;
    float u = c * (v + 0.044715f * v * v * v);
    return 0.5f * v * (1.0f + tanhf(u));
}

// ---------------- prep: x tf32-round + y zero ------------------------------
__global__ void k_prep(const float4* __restrict__ x, float4* __restrict__ y) {
    constexpr size_t NX = (size_t)TTOK * DDIM / 4;
    float4* xr4 = (float4*)g_xr;
    for (size_t i = (size_t)blockIdx.x * blockDim.x + threadIdx.x; i < 2 * NX;
         i += (size_t)gridDim.x * blockDim.x) {
        if (i < NX) {
            float4 v = x[i];
            float4 o;
            o.x = __uint_as_float(f2tf32(v.x));
            o.y = __uint_as_float(f2tf32(v.y));
            o.z = __uint_as_float(f2tf32(v.z));
            o.w = __uint_as_float(f2tf32(v.w));
            xr4[i] = o;
        } else {
            y[i - NX] = make_float4(0.f, 0.f, 0.f, 0.f);
        }
    }
}

// ---------------- fused routing + tile-table build (single block) ----------
__global__ void __launch_bounds__(1024)
k_routing(const float* __restrict__ p, const void* __restrict__ iv) {
    __shared__ int scnt[NLIST];
    __shared__ int s64;
    const int tid = threadIdx.x;
    if (tid < NLIST) scnt[tid] = 0;
    if (tid == 0) s64 = 1;
    __syncthreads();
    const int* q32 = (const int*)iv;
    int nz = 0;
    for (int i = tid; i < TTOK; i += 1024)
        if (q32[2 * i + 1] != 0) nz = 1;
    if (nz) s64 = 0;
    __syncthreads();
    const int is64 = s64;
    for (int t = tid; t < TTOK; t += 1024) {
        int e0, e1;
        if (is64) {
            const long long* q = (const long long*)iv;
            e0 = (int)q[2 * t]; e1 = (int)q[2 * t + 1];
        } else {
            e0 = q32[2 * t]; e1 = q32[2 * t + 1];
        }
        float p0 = p[2 * t], p1 = p[2 * t + 1];
        bool ok0 = (e0 >= 0 && e0 < NEXP), ok1 = (e1 >= 0 && e1 < NEXP);
        if (ok0 && ok1 && e0 == e1) {
            int pos = atomicAdd(&scnt[e0], 1);
            g_tok[e0 * TTOK + pos] = t;
            g_gate[e0 * TTOK + pos] = p0 + p1;
        } else {
            if (ok0) {
                int pos = atomicAdd(&scnt[e0], 1);
                g_tok[e0 * TTOK + pos] = t;
                g_gate[e0 * TTOK + pos] = p0;
            }
            if (ok1) {
                int L = 8 + e1;
                int pos = atomicAdd(&scnt[L], 1);
                g_tok[L * TTOK + pos] = t;
                g_gate[L * TTOK + pos] = p1;
            }
        }
    }
    __syncthreads();
    if (tid == 0) {
        int s = 0, nt = 0;
        for (int i = 0; i < NLIST; i++) {
            g_cnt[i] = scnt[i];
            g_off[i] = s;
            s += scnt[i];
            for (int m0 = 0; m0 < scnt[i]; m0 += BM) {
                g_tileL[nt] = i;
                g_tileM[nt] = m0;
                nt++;
            }
            if (i == 7) g_ntile0 = nt;   // slot-0 tiles are a table prefix
        }
        g_ntile = nt;
    }
}

// ---------------- mma.sync tf32 GEMM, 128x256 tile, 512 threads ------------
// P2=false: hbuf[off+i,:] = tf32(gelu(xr[tok,:] @ tf32(w1[e])))  K=DDIM
// P2=true : Y[tok,:]     += gate * (hbuf[off+i,:] @ tf32(w2[e])) K=HDIM
// 16 warps, 2(m)x8(n), warp tile 64x32. B raw [k][n], cvt.rna in-register.
template <bool P2>
__global__ void __launch_bounds__(NTHR)
k_gemm(const float* __restrict__ wsrc, float* __restrict__ yout, int sel) {
    constexpr int KD = P2 ? HDIM : DDIM;
    constexpr int WN = P2 ? DDIM : HDIM;
    int ti, tend;
    if (!P2) { ti = blockIdx.y; tend = g_ntile; }
    else if (sel == 0) { ti = blockIdx.y; tend = g_ntile0; }
    else { ti = g_ntile0 + blockIdx.y; tend = g_ntile; }
    if (ti >= tend) return;
    const int L = g_tileL[ti];
    const int m0 = g_tileM[ti];
    const int cnt = g_cnt[L];
    const int e = L & 7;
    const int n0 = blockIdx.x * BN;
    const int off = g_off[L];

    extern __shared__ float sm[];
    const uint32_t sm0 = smem_u32(sm);

    const int tid = threadIdx.x;
    // ---- fill mappings ----
    const int ra = tid >> 3, ca = tid & 7;        // A: rows ra+64i (i<2)
    const int kb = tid >> 6, nc = (tid & 63) * 4; // B: k-rows kb+8i (i<4)
    const float* aptr[2];
#pragma unroll
    for (int i = 0; i < 2; i++) {
        int m = ra + 64 * i;
        aptr[i] = P2 ? g_hbuf + (size_t)(off + m0 + m) * HDIM + ca * 4
                     : g_xr + (size_t)g_tok[L * TTOK + m0 + m] * DDIM + ca * 4;
    }
    const float* wbase = wsrc + (size_t)e * DDIM * HDIM +
                         (size_t)kb * WN + n0 + nc;

    auto issue = [&](int it) {
        const int s = it % NSTAGE;
        const uint32_t ab = sm0 + s * (STAGE_F * 4);
        const uint32_t bb = ab + BM * BKP * 4;
        const int k0 = it * BK;
#pragma unroll
        for (int i = 0; i < 2; i++)
            cpa16(ab + (uint32_t)(((ra + 64 * i) * BKP + ca * 4) * 4),
                  aptr[i] + k0);
#pragma unroll
        for (int i = 0; i < 4; i++)
            cpa16(bb + (uint32_t)(((kb + 8 * i) * BNP + nc) * 4),
                  wbase + (size_t)(k0 + 8 * i) * WN);
        asm volatile("cp.async.commit_group;" ::: "memory");
    };

    // ---- compute mapping: warp w -> rows wm..+63, cols wn..+31 ----
    const int w = tid >> 5, lane = tid & 31;
    const int wm = (w & 1) * 64, wn = (w >> 1) * 32;
    const int gr = lane >> 2, tc = lane & 3;

    float acc[4][4][4];
#pragma unroll
    for (int a = 0; a < 4; a++)
#pragma unroll
        for (int b = 0; b < 4; b++)
#pragma unroll
            for (int c = 0; c < 4; c++) acc[a][b][c] = 0.f;

    constexpr int NIT = KD / BK;
    issue(0);
    issue(1);

    for (int it = 0; it < NIT; it++) {
        if (it < NIT - 1)
            asm volatile("cp.async.wait_group 1;" ::: "memory");
        else
            asm volatile("cp.async.wait_group 0;" ::: "memory");
        __syncthreads();  // sole barrier: stage ready + prior readers drained
        if (it + 2 < NIT) issue(it + 2);  // overwrites stage (it-1)%3: safe
        const float* As = sm + (it % NSTAGE) * STAGE_F;
        const float* Bs = As + BM * BKP;
#pragma unroll
        for (int ks = 0; ks < 4; ks++) {
            const int kk = ks * 8;
            uint32_t af[4][4], bf[4][2];
#pragma unroll
            for (int mi = 0; mi < 4; mi++) {
                const float* ap = As + (wm + mi * 16 + gr) * BKP + kk + tc;
                af[mi][0] = __float_as_uint(ap[0]);
                af[mi][1] = __float_as_uint(ap[8 * BKP]);
                af[mi][2] = __float_as_uint(ap[4]);
                af[mi][3] = __float_as_uint(ap[8 * BKP + 4]);
            }
#pragma unroll
            for (int ni = 0; ni < 4; ni++) {
                const float* bp = Bs + (kk + tc) * BNP + wn + ni * 8 + gr;
                bf[ni][0] = u2tf32(__float_as_uint(bp[0]));
                bf[ni][1] = u2tf32(__float_as_uint(bp[4 * BNP]));
            }
#pragma unroll
            for (int mi = 0; mi < 4; mi++)
#pragma unroll
                for (int ni = 0; ni < 4; ni++)
                    mma8(acc[mi][ni], af[mi], bf[ni]);
        }
    }

    // ---- epilogue ----
#pragma unroll
    for (int half = 0; half < 2; half++) {
#pragma unroll
        for (int mi = 0; mi < 4; mi++) {
            const int lrow = wm + mi * 16 + gr + half * 8;
            if (m0 + lrow >= cnt) continue;
            if (!P2) {
                float* drow = g_hbuf + (size_t)(off + m0 + lrow) * HDIM + n0;
#pragma unroll
                for (int ni = 0; ni < 4; ni++) {
                    float2 o;
                    o.x = __uint_as_float(
                        f2tf32(gelu_tanh(acc[mi][ni][half * 2 + 0])));
                    o.y = __uint_as_float(
                        f2tf32(gelu_tanh(acc[mi][ni][half * 2 + 1])));
                    *(float2*)(drow + wn + ni * 8 + tc * 2) = o;
                }
            } else {
                const int tok = g_tok[L * TTOK + m0 + lrow];
                const float gate = g_gate[L * TTOK + m0 + lrow];
                float* drow = yout + (size_t)tok * DDIM + n0;
#pragma unroll
                for (int ni = 0; ni < 4; ni++) {
                    float2* dp = (float2*)(drow + wn + ni * 8 + tc * 2);
                    float2 o = *dp;
                    o.x += gate * acc[mi][ni][half * 2 + 0];
                    o.y += gate * acc[mi][ni][half * 2 + 1];
                    *dp = o;
                }
            }
        }
    }
}

// ---------------- launch ---------------------------------------------------
// Profiler captures launch index 3 -> k_gemm<true> slot 0 (GEMM2).
extern "C" void kernel_launch(void* const* d_in, const int* in_sizes, int n_in,
                              void* d_out, int out_size) {
    const float* x = (const float*)d_in[0];
    const float* p = (const float*)d_in[1];
    const void* idx = d_in[2];
    const float* w1 = (const float*)d_in[3];
    const float* w2 = (const float*)d_in[4];
    float* y = (float*)d_out;

    cudaFuncSetAttribute(k_gemm<false>,
                         cudaFuncAttributeMaxDynamicSharedMemorySize, SMEM_BYTES);
    cudaFuncSetAttribute(k_gemm<true>,
                         cudaFuncAttributeMaxDynamicSharedMemorySize, SMEM_BYTES);

    k_prep<<<2048, 256>>>((const float4*)x, (float4*)y);           // idx 0
    k_routing<<<1, 1024>>>(p, idx);                                // idx 1
    // GEMM1: worklist over all 16 lists (disjoint hbuf rows)      // idx 2
    k_gemm<false><<<dim3(HDIM / BN, 144), NTHR, SMEM_BYTES>>>(w1, nullptr, 0);
    // GEMM2: two slot-range launches (token <=1x per slot -> race-free RMW)
    k_gemm<true><<<dim3(DDIM / BN, 80), NTHR, SMEM_BYTES>>>(w2, y, 0);  // idx 3
    k_gemm<true><<<dim3(DDIM / BN, 80), NTHR, SMEM_BYTES>>>(w2, y, 1);  // idx 4
}

// round 17
// speedup vs baseline: 1.7040x; 1.7040x over previous
#include <cuda_runtime.h>
#include <cuda_fp16.h>
#include <math.h>
#include <stdint.h>

#define TTOK 8192
#define DDIM 2048
#define HDIM 8192
#define NEXP 8
#define NLIST 16
#define BM 128
#define BN 128
#define BK 32      // halves of K per stage
#define SPA 40     // smem row stride in halves: frag banks (4*gr+tc)%32 unique
#define STAGE_H ((BM + BN) * SPA)           // 10240 halves = 20480 B
#define NSTAGE 3
#define SMEM_BYTES (NSTAGE * STAGE_H * 2)   // 61440 B -> 2 CTAs/SM
#define MAXTILE 160

// ---------------- scratch (__device__ globals; no allocs) ------------------
__device__ int    g_cnt[NLIST];
__device__ int    g_off[NLIST];
__device__ int    g_ntile;
__device__ int    g_ntile0;
__device__ int    g_tileL[MAXTILE];
__device__ int    g_tileM[MAXTILE];
__device__ int    g_tok[NLIST * TTOK];
__device__ float  g_gate[NLIST * TTOK];
__device__ __half g_xh[(size_t)TTOK * DDIM];                // fp16 x
__device__ __half g_w1h[(size_t)NEXP * HDIM * DDIM];        // fp16 w1 [e][h][d]
__device__ __half g_w2h[(size_t)NEXP * DDIM * HDIM];        // fp16 w2 [e][d][h]
__device__ __half g_hbuf[(size_t)(2 * TTOK + BM) * HDIM];   // fp16 packed rows

// ---------------- helpers --------------------------------------------------
__device__ __forceinline__ uint32_t smem_u32(const void* p) {
    uint32_t a;
    asm("{ .reg .u64 t; cvta.to.shared.u64 t, %1; cvt.u32.u64 %0, t; }"
        : "=r"(a) : "l"(p));
    return a;
}
__device__ __forceinline__ void cpa16(uint32_t s, const void* g) {
    asm volatile("cp.async.cg.shared.global [%0], [%1], 16;"
                 :: "r"(s), "l"(g) : "memory");
}
__device__ __forceinline__ void mma16(float* c, const uint32_t* a,
                                      const uint32_t* b) {
    asm volatile(
        "mma.sync.aligned.m16n8k16.row.col.f32.f16.f16.f32 "
        "{%0,%1,%2,%3}, {%4,%5,%6,%7}, {%8,%9}, {%0,%1,%2,%3};"
        : "+f"(c[0]), "+f"(c[1]), "+f"(c[2]), "+f"(c[3])
        : "r"(a[0]), "r"(a[1]), "r"(a[2]), "r"(a[3]), "r"(b[0]), "r"(b[1]));
}
__device__ __forceinline__ float gelu_tanh(float v) {
    const float c = 0.7978845608028654f;
    float u = c * (v + 0.044715f * v * v * v);
    return 0.5f * v * (1.0f + tanhf(u));
}

// ---------------- weight transpose + fp16 convert --------------------------
// W2=false: w1 [e][d][h] -> g_w1h [e][h][d]; W2=true: w2 [e][h][d] -> g_w2h
template <bool W2>
__global__ void k_wconv(const float* __restrict__ in) {
    constexpr int R = W2 ? HDIM : DDIM;   // k extent (rows in)
    constexpr int C = W2 ? DDIM : HDIM;   // n extent (cols in)
    __half* out = W2 ? g_w2h : g_w1h;
    __shared__ float t[32][33];
    size_t zo = (size_t)blockIdx.z * R * C;
    int c0 = blockIdx.x * 32, r0 = blockIdx.y * 32;
    int tx = threadIdx.x, ty = threadIdx.y;
#pragma unroll
    for (int j = 0; j < 32; j += 8)
        t[ty + j][tx] = in[zo + (size_t)(r0 + ty + j) * C + c0 + tx];
    __syncthreads();
#pragma unroll
    for (int j = 0; j < 32; j += 8)
        out[zo + (size_t)(c0 + ty + j) * R + r0 + tx] =
            __float2half_rn(t[tx][ty + j]);
}

// ---------------- prep: x -> fp16 + y zero ---------------------------------
__global__ void k_prep(const float4* __restrict__ x, float4* __restrict__ y) {
    constexpr size_t NX = (size_t)TTOK * DDIM / 4;
    __half2* xh2 = (__half2*)g_xh;
    for (size_t i = (size_t)blockIdx.x * blockDim.x + threadIdx.x; i < 2 * NX;
         i += (size_t)gridDim.x * blockDim.x) {
        if (i < NX) {
            float4 v = x[i];
            xh2[2 * i + 0] = __floats2half2_rn(v.x, v.y);
            xh2[2 * i + 1] = __floats2half2_rn(v.z, v.w);
        } else {
            y[i - NX] = make_float4(0.f, 0.f, 0.f, 0.f);
        }
    }
}

// ---------------- fused routing + tile-table build (single block) ----------
__global__ void __launch_bounds__(1024)
k_routing(const float* __restrict__ p, const void* __restrict__ iv) {
    __shared__ int scnt[NLIST];
    __shared__ int s64;
    const int tid = threadIdx.x;
    if (tid < NLIST) scnt[tid] = 0;
    if (tid == 0) s64 = 1;
    __syncthreads();
    const int* q32 = (const int*)iv;
    int nz = 0;
    for (int i = tid; i < TTOK; i += 1024)
        if (q32[2 * i + 1] != 0) nz = 1;
    if (nz) s64 = 0;
    __syncthreads();
    const int is64 = s64;
    for (int t = tid; t < TTOK; t += 1024) {
        int e0, e1;
        if (is64) {
            const long long* q = (const long long*)iv;
            e0 = (int)q[2 * t]; e1 = (int)q[2 * t + 1];
        } else {
            e0 = q32[2 * t]; e1 = q32[2 * t + 1];
        }
        float p0 = p[2 * t], p1 = p[2 * t + 1];
        bool ok0 = (e0 >= 0 && e0 < NEXP), ok1 = (e1 >= 0 && e1 < NEXP);
        if (ok0 && ok1 && e0 == e1) {
            int pos = atomicAdd(&scnt[e0], 1);
            g_tok[e0 * TTOK + pos] = t;
            g_gate[e0 * TTOK + pos] = p0 + p1;
        } else {
            if (ok0) {
                int pos = atomicAdd(&scnt[e0], 1);
                g_tok[e0 * TTOK + pos] = t;
                g_gate[e0 * TTOK + pos] = p0;
            }
            if (ok1) {
                int L = 8 + e1;
                int pos = atomicAdd(&scnt[L], 1);
                g_tok[L * TTOK + pos] = t;
                g_gate[L * TTOK + pos] = p1;
            }
        }
    }
    __syncthreads();
    if (tid == 0) {
        int s = 0, nt = 0;
        for (int i = 0; i < NLIST; i++) {
            g_cnt[i] = scnt[i];
            g_off[i] = s;
            s += scnt[i];
            for (int m0 = 0; m0 < scnt[i]; m0 += BM) {
                g_tileL[nt] = i;
                g_tileM[nt] = m0;
                nt++;
            }
            if (i == 7) g_ntile0 = nt;
        }
        g_ntile = nt;
    }
}

// ---------------- fp16 mma.sync GEMM, 128x128, 3-stage, 2 CTA/SM -----------
// P2=false: hbuf[off+i,:] = fp16(gelu(xh[tok,:] @ w1h[e]^T))  K=DDIM
// P2=true : Y[tok,:]     += gate * (hbuf[off+i,:] @ w2h[e]^T) K=HDIM
// A smem [m][k], B smem [n][k] (both k-contiguous fp16 rows, stride SPA).
template <bool P2>
__global__ void __launch_bounds__(256, 2)
k_gemm(float* __restrict__ yout, int sel) {
    constexpr int KD = P2 ? HDIM : DDIM;
    int ti, tend;
    if (!P2) { ti = blockIdx.y; tend = g_ntile; }
    else if (sel == 0) { ti = blockIdx.y; tend = g_ntile0; }
    else { ti = g_ntile0 + blockIdx.y; tend = g_ntile; }
    if (ti >= tend) return;
    const int L = g_tileL[ti];
    const int m0 = g_tileM[ti];
    const int cnt = g_cnt[L];
    const int e = L & 7;
    const int n0 = blockIdx.x * BN;
    const int off = g_off[L];

    extern __shared__ __half sm[];
    const uint32_t sm0 = smem_u32(sm);

    const int tid = threadIdx.x;
    // ---- fill mappings: rows fr(+64), 16B chunk fc (8 halves) ----
    const int fr = tid >> 2, fc = (tid & 3) * 8;
    const __half* aptr[2];
    const __half* bptr[2];
    const __half* wt = (P2 ? g_w2h : g_w1h) + (size_t)e * DDIM * HDIM;
#pragma unroll
    for (int i = 0; i < 2; i++) {
        int m = fr + 64 * i;
        aptr[i] = P2 ? g_hbuf + (size_t)(off + m0 + m) * HDIM + fc
                     : g_xh + (size_t)g_tok[L * TTOK + m0 + m] * DDIM + fc;
        bptr[i] = wt + (size_t)(n0 + m) * KD + fc;
    }

    auto issue = [&](int it) {
        const int s = it % NSTAGE;
        const uint32_t ab = sm0 + s * (STAGE_H * 2);
        const uint32_t bb = ab + BM * SPA * 2;
        const int k0 = it * BK;
#pragma unroll
        for (int i = 0; i < 2; i++) {
            cpa16(ab + (uint32_t)(((fr + 64 * i) * SPA + fc) * 2),
                  aptr[i] + k0);
            cpa16(bb + (uint32_t)(((fr + 64 * i) * SPA + fc) * 2),
                  bptr[i] + k0);
        }
        asm volatile("cp.async.commit_group;" ::: "memory");
    };

    // ---- compute mapping: warp w -> rows wm..+63, cols wn..+31 ----
    const int w = tid >> 5, lane = tid & 31;
    const int wm = (w & 1) * 64, wn = (w >> 1) * 32;
    const int gr = lane >> 2, tc = lane & 3;

    float acc[4][4][4];
#pragma unroll
    for (int a = 0; a < 4; a++)
#pragma unroll
        for (int b = 0; b < 4; b++)
#pragma unroll
            for (int c = 0; c < 4; c++) acc[a][b][c] = 0.f;

    constexpr int NIT = KD / BK;
    issue(0);
    issue(1);

    for (int it = 0; it < NIT; it++) {
        if (it < NIT - 1)
            asm volatile("cp.async.wait_group 1;" ::: "memory");
        else
            asm volatile("cp.async.wait_group 0;" ::: "memory");
        __syncthreads();  // sole barrier
        if (it + 2 < NIT) issue(it + 2);
        const __half* As = sm + (it % NSTAGE) * STAGE_H;
        const __half* Bs = As + BM * SPA;
#pragma unroll
        for (int ks = 0; ks < 2; ks++) {
            const int kk = ks * 16;
            uint32_t af[4][4], bf[4][2];
#pragma unroll
            for (int mi = 0; mi < 4; mi++) {
                const __half* ap = As + (wm + mi * 16 + gr) * SPA + kk + 2 * tc;
                af[mi][0] = *(const uint32_t*)(ap);
                af[mi][1] = *(const uint32_t*)(ap + 8 * SPA);
                af[mi][2] = *(const uint32_t*)(ap + 8);
                af[mi][3] = *(const uint32_t*)(ap + 8 * SPA + 8);
            }
#pragma unroll
            for (int ni = 0; ni < 4; ni++) {
                const __half* bp = Bs + (wn + ni * 8 + gr) * SPA + kk + 2 * tc;
                bf[ni][0] = *(const uint32_t*)(bp);
                bf[ni][1] = *(const uint32_t*)(bp + 8);
            }
#pragma unroll
            for (int mi = 0; mi < 4; mi++)
#pragma unroll
                for (int ni = 0; ni < 4; ni++)
                    mma16(acc[mi][ni], af[mi], bf[ni]);
        }
    }

    // ---- epilogue ----
#pragma unroll
    for (int half = 0; half < 2; half++) {
#pragma unroll
        for (int mi = 0; mi < 4; mi++) {
            const int lrow = wm + mi * 16 + gr + half * 8;
            if (m0 + lrow >= cnt) continue;
            if (!P2) {
                __half* drow = g_hbuf + (size_t)(off + m0 + lrow) * HDIM + n0;
#pragma unroll
                for (int ni = 0; ni < 4; ni++) {
                    float ox = gelu_tanh(acc[mi][ni][half * 2 + 0]);
                    float oy = gelu_tanh(acc[mi][ni][half * 2 + 1]);
                    *(__half2*)(drow + wn + ni * 8 + tc * 2) =
                        __floats2half2_rn(ox, oy);
                }
            } else {
                const int tok = g_tok[L * TTOK + m0 + lrow];
                const float gate = g_gate[L * TTOK + m0 + lrow];
                float* drow = yout + (size_t)tok * DDIM + n0;
#pragma unroll
                for (int ni = 0; ni < 4; ni++) {
                    float2* dp = (float2*)(drow + wn + ni * 8 + tc * 2);
                    float2 o = *dp;
                    o.x += gate * acc[mi][ni][half * 2 + 0];
                    o.y += gate * acc[mi][ni][half * 2 + 1];
                    *dp = o;
                }
            }
        }
    }
}

// ---------------- launch ---------------------------------------------------
// Profiler captures launch index 3 -> k_gemm<false> (GEMM1).
extern "C" void kernel_launch(void* const* d_in, const int* in_sizes, int n_in,
                              void* d_out, int out_size) {
    const float* x = (const float*)d_in[0];
    const float* p = (const float*)d_in[1];
    const void* idx = d_in[2];
    const float* w1 = (const float*)d_in[3];
    const float* w2 = (const float*)d_in[4];
    float* y = (float*)d_out;

    cudaFuncSetAttribute(k_gemm<false>,
                         cudaFuncAttributeMaxDynamicSharedMemorySize, SMEM_BYTES);
    cudaFuncSetAttribute(k_gemm<true>,
                         cudaFuncAttributeMaxDynamicSharedMemorySize, SMEM_BYTES);

    // w1 convert first (needed by GEMM1); w2 convert overlaps after GEMM1 issue
    k_wconv<false><<<dim3(HDIM / 32, DDIM / 32, NEXP), dim3(32, 8)>>>(w1); // 0
    k_prep<<<2048, 256>>>((const float4*)x, (float4*)y);                   // 1
    k_routing<<<1, 1024>>>(p, idx);                                        // 2
    // GEMM1: worklist over all 16 lists (disjoint hbuf rows)              // 3
    k_gemm<false><<<dim3(HDIM / BN, 144), 256, SMEM_BYTES>>>(nullptr, 0);
    k_wconv<true><<<dim3(DDIM / 32, HDIM / 32, NEXP), dim3(32, 8)>>>(w2);  // 4
    // GEMM2: two slot-range launches (token <=1x per slot -> race-free RMW)
    k_gemm<true><<<dim3(DDIM / BN, 80), 256, SMEM_BYTES>>>(y, 0);          // 5
    k_gemm<true><<<dim3(DDIM / BN, 80), 256, SMEM_BYTES>>>(y, 1);          // 6
}